// round 1
// baseline (speedup 1.0000x reference)
#include <cuda_runtime.h>

#define CHN   4
#define HHT   128
#define WWD   128
#define TT    50
#define TP    53          // padded t-stride in smem: gcd(53,32)=1 -> conflict-free
#define NBATCH 8
#define NPIX  (NBATCH*CHN*HHT*WWD)   // 524288
#define NELEM (NPIX*TT)              // 26214400

// Scratch ping-pong buffers (allocation in kernel_launch is forbidden).
__device__ float g_bufA[NELEM];
__device__ float g_bufB[NELEM];

// ---------------------------------------------------------------------------
// Pointwise-temporal kernels: one thread = one (n,c,h,w) pixel, serial over T.
// ---------------------------------------------------------------------------

// alpha PSP: out[t] = coef*s2 ; s1 = r*s1 + x[t] ; s2 = r*s2 + r*s1
__global__ void psp_kernel(const float* __restrict__ in, float* __restrict__ out,
                           float r, float coef) {
    int pix = blockIdx.x * blockDim.x + threadIdx.x;
    if (pix >= NPIX) return;
    int base = pix * TT;
    float s1 = 0.f, s2 = 0.f;
#pragma unroll
    for (int t = 0; t < TT; ++t) {
        float x = in[base + t];
        out[base + t] = coef * s2;
        s1 = fmaf(r, s1, x);
        s2 = fmaf(r, s2, r * s1);
    }
}

// spike dynamics fused with the NEXT layer's alpha PSP.
// m[t] = u[t] + coefR*sd2 ; s = (m>=theta) ; refractory states update;
// out[t] = coefP*sp2 (psp of spike train, spikes <= t-1) ; psp states update.
__global__ void spike_psp_kernel(const float* __restrict__ u, float* __restrict__ out,
                                 float rR, float coefR, float theta,
                                 float rP, float coefP) {
    int pix = blockIdx.x * blockDim.x + threadIdx.x;
    if (pix >= NPIX) return;
    int base = pix * TT;
    float sd1 = 0.f, sd2 = 0.f, sp1 = 0.f, sp2 = 0.f;
#pragma unroll
    for (int t = 0; t < TT; ++t) {
        float m = fmaf(coefR, sd2, u[base + t]);
        float s = (m >= theta) ? 1.f : 0.f;
        sd1 = fmaf(rR, sd1, s);
        sd2 = fmaf(rR, sd2, rR * sd1);
        out[base + t] = coefP * sp2;
        sp1 = fmaf(rP, sp1, s);
        sp2 = fmaf(rP, sp2, rP * sp1);
    }
}

// final spike dynamics -> binary output
__global__ void spike_out_kernel(const float* __restrict__ u, float* __restrict__ out,
                                 float rR, float coefR, float theta) {
    int pix = blockIdx.x * blockDim.x + threadIdx.x;
    if (pix >= NPIX) return;
    int base = pix * TT;
    float sd1 = 0.f, sd2 = 0.f;
#pragma unroll
    for (int t = 0; t < TT; ++t) {
        float m = fmaf(coefR, sd2, u[base + t]);
        float s = (m >= theta) ? 1.f : 0.f;
        sd1 = fmaf(rR, sd1, s);
        sd2 = fmaf(rR, sd2, rR * sd1);
        out[base + t] = s;
    }
}

// ---------------------------------------------------------------------------
// Per-timestep 2D conv (cross-correlation), KxK, CHN->CHN, zero pad K/2.
// Block = (n, h, 32-wide w strip). Full T handled in-block.
// SMEM patch: [ci][kh][w(32+2P)][t(TP=53 padded)], weights repacked [ci][kh][kw][co].
// Thread (wl = tid&31, tq = tid>>5) accumulates t0..t0+3 x 4 co in registers.
// ---------------------------------------------------------------------------
template <int K>
__global__ void __launch_bounds__(416, 1)
conv_kernel(const float* __restrict__ in, const float* __restrict__ wts,
            float* __restrict__ out) {
    constexpr int PAD = K / 2;
    constexpr int WH  = 32 + 2 * PAD;
    constexpr int NT  = 416;
    constexpr int SIN = CHN * K * WH * TP;

    extern __shared__ float sm[];
    float* s_in = sm;          // SIN floats
    float* s_w  = sm + SIN;    // CHN*K*K*4 floats (16B aligned: SIN%4==0)

    const int tid = threadIdx.x;
    const int w0  = blockIdx.x * 32;
    const int h   = blockIdx.y;
    const int n   = blockIdx.z;

    // zero patch (covers halo out-of-range + t padding)
    for (int e = tid; e < SIN; e += NT) s_in[e] = 0.f;
    // weights: global OIHW [co][ci][kh][kw] -> smem [ci][kh][kw][co]
    for (int e = tid; e < CHN * CHN * K * K; e += NT) {
        int co = e / (CHN * K * K);
        int r  = e % (CHN * K * K);
        s_w[r * 4 + co] = wts[e];
    }
    __syncthreads();

    // load input rows: (w,t) contiguous span per (ci, kh)
    for (int ci = 0; ci < CHN; ++ci) {
#pragma unroll
        for (int kh = 0; kh < K; ++kh) {
            int hh = h + kh - PAD;
            if (hh < 0 || hh >= HHT) continue;
            const float* src = in + (((n * CHN + ci) * HHT + hh) * WWD + (w0 - PAD)) * TT;
            float* dst = s_in + (ci * K + kh) * WH * TP;
            for (int e = tid; e < WH * TT; e += NT) {
                int wl = e / TT, t = e % TT;
                int wg = w0 - PAD + wl;
                if (wg < 0 || wg >= WWD) continue;
                dst[wl * TP + t] = src[e];
            }
        }
    }
    __syncthreads();

    const int wl = tid & 31;
    const int tq = tid >> 5;   // 0..12
    const int t0 = tq * 4;

    float acc[4][4];
#pragma unroll
    for (int i = 0; i < 4; ++i)
#pragma unroll
        for (int j = 0; j < 4; ++j) acc[i][j] = 0.f;

#pragma unroll 1
    for (int ci = 0; ci < CHN; ++ci) {
#pragma unroll
        for (int kh = 0; kh < K; ++kh) {
            const float* rowp = s_in + ((ci * K + kh) * WH + wl) * TP + t0;
            const float* wp   = s_w + (ci * K + kh) * K * 4;
#pragma unroll
            for (int kw = 0; kw < K; ++kw) {
                const float4 wv = *(const float4*)(wp + kw * 4);   // broadcast
                const float* ip = rowp + kw * TP;                  // conflict-free
#pragma unroll
                for (int tt = 0; tt < 4; ++tt) {
                    float v = ip[tt];
                    acc[tt][0] = fmaf(v, wv.x, acc[tt][0]);
                    acc[tt][1] = fmaf(v, wv.y, acc[tt][1]);
                    acc[tt][2] = fmaf(v, wv.z, acc[tt][2]);
                    acc[tt][3] = fmaf(v, wv.w, acc[tt][3]);
                }
            }
        }
    }
    __syncthreads();

    // stage results so the global store is fully coalesced
    float* s_out = sm;  // overlay: 4 * 1600 floats << SIN
#pragma unroll
    for (int tt = 0; tt < 4; ++tt) {
        int t = t0 + tt;
        if (t < TT) {
#pragma unroll
            for (int co = 0; co < 4; ++co)
                s_out[co * (32 * TT) + wl * TT + t] = acc[tt][co];
        }
    }
    __syncthreads();

    for (int e = tid; e < 4 * 32 * TT; e += NT) {
        int co  = e / (32 * TT);
        int rem = e % (32 * TT);   // = wl*TT + t, contiguous in global
        out[(((n * CHN + co) * HHT + h) * WWD + w0) * TT + rem] = s_out[e];
    }
}

// ---------------------------------------------------------------------------

extern "C" void kernel_launch(void* const* d_in, const int* in_sizes, int n_in,
                              void* d_out, int out_size) {
    const float* x  = (const float*)d_in[0];
    const float* w1 = (const float*)d_in[1];
    const float* w2 = (const float*)d_in[2];
    float* outp = (float*)d_out;

    float *bufA, *bufB;
    cudaGetSymbolAddress((void**)&bufA, g_bufA);
    cudaGetSymbolAddress((void**)&bufB, g_bufB);

    const int SMEM5 = (CHN * 5 * 36 * TP + CHN * CHN * 25) * 4;  // 154240 B
    const int SMEM3 = (CHN * 3 * 34 * TP + CHN * CHN * 9) * 4;   //  87072 B
    cudaFuncSetAttribute(conv_kernel<5>, cudaFuncAttributeMaxDynamicSharedMemorySize, SMEM5);
    cudaFuncSetAttribute(conv_kernel<3>, cudaFuncAttributeMaxDynamicSharedMemorySize, SMEM3);

    // constants (double -> float, matching jnp.float32(np.exp(...)))
    const float r1    = (float)0.36787944117144233;   // exp(-1)
    const float cP1   = (float)2.718281828459045;     // e/1
    const float rR1   = (float)0.36787944117144233;   // exp(-1/tauRef1)
    const float cR1   = (float)(-54.365636569180902); // -1*20*e/1
    const float th1   = 20.0f;
    const float r2    = (float)0.6065306597126334;    // exp(-1/2)
    const float cP2   = (float)1.3591409142295225;    // e/2
    const float rR2   = (float)0.6065306597126334;    // exp(-1/tauRef2)
    const float cR2   = (float)(-54.365636569180902); // -1*40*e/2
    const float th2   = 40.0f;

    const int PBLK = 256, PGRID = NPIX / PBLK;  // 2048
    dim3 cgrid(WWD / 32, HHT, NBATCH);          // (4,128,8)

    psp_kernel      <<<PGRID, PBLK>>>(x,    bufA, r1, cP1);
    conv_kernel<5>  <<<cgrid, 416, SMEM5>>>(bufA, w1, bufB);
    spike_psp_kernel<<<PGRID, PBLK>>>(bufB, bufA, rR1, cR1, th1, r2, cP2);
    conv_kernel<3>  <<<cgrid, 416, SMEM3>>>(bufA, w2, bufB);
    spike_out_kernel<<<PGRID, PBLK>>>(bufB, outp, rR2, cR2, th2);
}

// round 2
// speedup vs baseline: 2.3583x; 2.3583x over previous
#include <cuda_runtime.h>

#define CHN   4
#define HHT   128
#define WWD   128
#define TT    50
#define TP    52          // padded t-stride: mult of 4 (LDS.128) & conflict-free @ stride 52
#define NBATCH 8
#define NPIX  (NBATCH*CHN*HHT*WWD)   // 524288
#define NELEM (NPIX*TT)              // 26214400

__device__ float g_bufA[NELEM];
__device__ float g_bufB[NELEM];

// ---------------------------------------------------------------------------
// Pointwise-temporal kernels with warp-local smem transpose.
// Block = 256 threads (8 warps); each warp owns 32 consecutive pixels.
// Load coalesced -> smem [32][53] -> per-lane recurrence on own row -> store.
// ---------------------------------------------------------------------------
#define PW_PAD 53    // row stride in transpose tile: gcd(53,32)=1 -> conflict-free
#define PW_WARPS 8
#define PW_SMEM (PW_WARPS * 32 * PW_PAD * 4)

__device__ __forceinline__ void pw_load(float* ws, const float* g, int lane) {
#pragma unroll
    for (int w = 0; w < 32; ++w) {
        ws[w * PW_PAD + lane] = g[w * TT + lane];
        if (lane < TT - 32) ws[w * PW_PAD + 32 + lane] = g[w * TT + 32 + lane];
    }
}
__device__ __forceinline__ void pw_store(float* out, const float* ws, int lane) {
#pragma unroll
    for (int w = 0; w < 32; ++w) {
        out[w * TT + lane] = ws[w * PW_PAD + lane];
        if (lane < TT - 32) out[w * TT + 32 + lane] = ws[w * PW_PAD + 32 + lane];
    }
}

__global__ void __launch_bounds__(256) psp_kernel(const float* __restrict__ in,
                                                  float* __restrict__ out,
                                                  float r, float coef) {
    extern __shared__ float sm[];
    const int lane = threadIdx.x & 31;
    const int wrp  = threadIdx.x >> 5;
    float* ws = sm + wrp * 32 * PW_PAD;
    const long base = (long)(blockIdx.x * (PW_WARPS * 32) + wrp * 32) * TT;
    pw_load(ws, in + base, lane);
    __syncwarp();
    float* row = ws + lane * PW_PAD;
    float s1 = 0.f, s2 = 0.f;
#pragma unroll
    for (int t = 0; t < TT; ++t) {
        float x = row[t];
        row[t] = coef * s2;
        s1 = fmaf(r, s1, x);
        s2 = fmaf(r, s2, r * s1);
    }
    __syncwarp();
    pw_store(out + base, ws, lane);
}

__global__ void __launch_bounds__(256) spike_psp_kernel(const float* __restrict__ u,
                                                        float* __restrict__ out,
                                                        float rR, float coefR, float theta,
                                                        float rP, float coefP) {
    extern __shared__ float sm[];
    const int lane = threadIdx.x & 31;
    const int wrp  = threadIdx.x >> 5;
    float* ws = sm + wrp * 32 * PW_PAD;
    const long base = (long)(blockIdx.x * (PW_WARPS * 32) + wrp * 32) * TT;
    pw_load(ws, u + base, lane);
    __syncwarp();
    float* row = ws + lane * PW_PAD;
    float sd1 = 0.f, sd2 = 0.f, sp1 = 0.f, sp2 = 0.f;
#pragma unroll
    for (int t = 0; t < TT; ++t) {
        float m = fmaf(coefR, sd2, row[t]);
        float s = (m >= theta) ? 1.f : 0.f;
        sd1 = fmaf(rR, sd1, s);
        sd2 = fmaf(rR, sd2, rR * sd1);
        row[t] = coefP * sp2;
        sp1 = fmaf(rP, sp1, s);
        sp2 = fmaf(rP, sp2, rP * sp1);
    }
    __syncwarp();
    pw_store(out + base, ws, lane);
}

__global__ void __launch_bounds__(256) spike_out_kernel(const float* __restrict__ u,
                                                        float* __restrict__ out,
                                                        float rR, float coefR, float theta) {
    extern __shared__ float sm[];
    const int lane = threadIdx.x & 31;
    const int wrp  = threadIdx.x >> 5;
    float* ws = sm + wrp * 32 * PW_PAD;
    const long base = (long)(blockIdx.x * (PW_WARPS * 32) + wrp * 32) * TT;
    pw_load(ws, u + base, lane);
    __syncwarp();
    float* row = ws + lane * PW_PAD;
    float sd1 = 0.f, sd2 = 0.f;
#pragma unroll
    for (int t = 0; t < TT; ++t) {
        float m = fmaf(coefR, sd2, row[t]);
        float s = (m >= theta) ? 1.f : 0.f;
        sd1 = fmaf(rR, sd1, s);
        sd2 = fmaf(rR, sd2, rR * sd1);
        row[t] = s;
    }
    __syncwarp();
    pw_store(out + base, ws, lane);
}

// ---------------------------------------------------------------------------
// Per-timestep 2D conv KxK, CHN->CHN, zero pad K/2, cross-correlation.
// Block = (32-wide w strip, h, n), 416 threads = 13 warps.
// ci processed in passes of CIH channels to fit 2 blocks/SM in smem.
// SMEM patch [ciL][kh][w(32+2P)][t(TP=52)]; weights [ci][kh][kw][co] (float4).
// Thread (wl=tid&31, tq=tid>>5): acc over 4 t's (t0=4*tq, aligned -> LDS.128)
// x 4 output channels. Fully unrolled taps: LDS immediate offsets, no ALU.
// ---------------------------------------------------------------------------
template <int K, int CIH>
__global__ void __launch_bounds__(416, 2)
conv_kernel(const float* __restrict__ in, const float* __restrict__ wts,
            float* __restrict__ out) {
    constexpr int PAD = K / 2;
    constexpr int WH  = 32 + 2 * PAD;
    constexpr int NT  = 416;
    constexpr int SIN = CIH * K * WH * TP;
    constexpr int NW  = CHN * CHN * K * K;

    extern __shared__ float sm[];
    float* s_in = sm;
    float* s_w  = sm + SIN;

    const int tid  = threadIdx.x;
    const int lane = tid & 31;
    const int wrp  = tid >> 5;
    const int w0   = blockIdx.x * 32;
    const int h    = blockIdx.y;
    const int n    = blockIdx.z;

    // weights: OIHW [co][ci][kh][kw] -> smem [(ci,kh,kw)][co]
    if (tid < NW) {
        int co = tid / (CHN * K * K);
        int r  = tid % (CHN * K * K);
        s_w[r * 4 + co] = wts[tid];
    }

    const int wl = lane;
    const int t0 = wrp * 4;

    float acc[4][4];
#pragma unroll
    for (int i = 0; i < 4; ++i)
#pragma unroll
        for (int j = 0; j < 4; ++j) acc[i][j] = 0.f;

#pragma unroll
    for (int cib = 0; cib < CHN; cib += CIH) {
        // zero the patch (halo rows / t padding)
        for (int e = tid; e < SIN; e += NT) s_in[e] = 0.f;
        __syncthreads();
        // fill rows: warp-per-row structured copy, pure adds
        for (int ci = 0; ci < CIH; ++ci) {
#pragma unroll
            for (int kh = 0; kh < K; ++kh) {
                int hh = h + kh - PAD;
                if (hh < 0 || hh >= HHT) continue;
                const float* src = in + (((long)(n * CHN + cib + ci) * HHT + hh) * WWD + (w0 - PAD)) * TT;
                float* dst = s_in + (ci * K + kh) * WH * TP;
                for (int row = wrp; row < WH; row += 13) {
                    int wg = w0 - PAD + row;
                    if (wg >= 0 && wg < WWD) {
                        dst[row * TP + lane] = src[row * TT + lane];
                        if (lane < TT - 32)
                            dst[row * TP + 32 + lane] = src[row * TT + 32 + lane];
                    }
                }
            }
        }
        __syncthreads();
        // accumulate: fully unrolled, LDS.128 + FFMA only
#pragma unroll
        for (int ci = 0; ci < CIH; ++ci) {
#pragma unroll
            for (int kh = 0; kh < K; ++kh) {
                const float* rowp = s_in + ((ci * K + kh) * WH + wl) * TP + t0;
                const float* wp   = s_w + ((cib + ci) * K + kh) * K * 4;
#pragma unroll
                for (int kw = 0; kw < K; ++kw) {
                    const float4 wv = *(const float4*)(wp + kw * 4);     // broadcast
                    const float4 iv = *(const float4*)(rowp + kw * TP);  // LDS.128
                    acc[0][0] = fmaf(iv.x, wv.x, acc[0][0]);
                    acc[0][1] = fmaf(iv.x, wv.y, acc[0][1]);
                    acc[0][2] = fmaf(iv.x, wv.z, acc[0][2]);
                    acc[0][3] = fmaf(iv.x, wv.w, acc[0][3]);
                    acc[1][0] = fmaf(iv.y, wv.x, acc[1][0]);
                    acc[1][1] = fmaf(iv.y, wv.y, acc[1][1]);
                    acc[1][2] = fmaf(iv.y, wv.z, acc[1][2]);
                    acc[1][3] = fmaf(iv.y, wv.w, acc[1][3]);
                    acc[2][0] = fmaf(iv.z, wv.x, acc[2][0]);
                    acc[2][1] = fmaf(iv.z, wv.y, acc[2][1]);
                    acc[2][2] = fmaf(iv.z, wv.z, acc[2][2]);
                    acc[2][3] = fmaf(iv.z, wv.w, acc[2][3]);
                    acc[3][0] = fmaf(iv.w, wv.x, acc[3][0]);
                    acc[3][1] = fmaf(iv.w, wv.y, acc[3][1]);
                    acc[3][2] = fmaf(iv.w, wv.z, acc[3][2]);
                    acc[3][3] = fmaf(iv.w, wv.w, acc[3][3]);
                }
            }
        }
        __syncthreads();
    }

    // stage results through smem for fully coalesced global stores
    float* s_out = sm;  // 4*32*50 = 6400 floats << SIN
#pragma unroll
    for (int tt = 0; tt < 4; ++tt) {
        int t = t0 + tt;
        if (t < TT) {
#pragma unroll
            for (int co = 0; co < 4; ++co)
                s_out[co * (32 * TT) + wl * TT + t] = acc[tt][co];
        }
    }
    __syncthreads();

    for (int e = tid; e < 4 * 32 * TT; e += NT) {
        int co  = e / (32 * TT);
        int rem = e - co * (32 * TT);   // = wl*TT + t, contiguous in global
        out[(((long)(n * CHN + co) * HHT + h) * WWD + w0) * TT + rem] = s_out[e];
    }
}

// ---------------------------------------------------------------------------

extern "C" void kernel_launch(void* const* d_in, const int* in_sizes, int n_in,
                              void* d_out, int out_size) {
    const float* x  = (const float*)d_in[0];
    const float* w1 = (const float*)d_in[1];
    const float* w2 = (const float*)d_in[2];
    float* outp = (float*)d_out;

    float *bufA, *bufB;
    cudaGetSymbolAddress((void**)&bufA, g_bufA);
    cudaGetSymbolAddress((void**)&bufB, g_bufB);

    const int SMEM5 = (2 * 5 * 36 * TP + CHN * CHN * 25) * 4;  // ~76.5 KB -> 2 blocks/SM
    const int SMEM3 = (4 * 3 * 34 * TP + CHN * CHN * 9) * 4;   // ~85.4 KB -> 2 blocks/SM
    cudaFuncSetAttribute(conv_kernel<5, 2>, cudaFuncAttributeMaxDynamicSharedMemorySize, SMEM5);
    cudaFuncSetAttribute(conv_kernel<3, 4>, cudaFuncAttributeMaxDynamicSharedMemorySize, SMEM3);
    cudaFuncSetAttribute(psp_kernel,       cudaFuncAttributeMaxDynamicSharedMemorySize, PW_SMEM);
    cudaFuncSetAttribute(spike_psp_kernel, cudaFuncAttributeMaxDynamicSharedMemorySize, PW_SMEM);
    cudaFuncSetAttribute(spike_out_kernel, cudaFuncAttributeMaxDynamicSharedMemorySize, PW_SMEM);

    const float r1  = (float)0.36787944117144233;   // exp(-1/tau1)
    const float cP1 = (float)2.718281828459045;     // e/tau1
    const float rR1 = (float)0.36787944117144233;   // exp(-1/tauRef1)
    const float cR1 = (float)(-54.365636569180902); // -scaleRef*theta1*e/tauRef1
    const float th1 = 20.0f;
    const float r2  = (float)0.6065306597126334;    // exp(-1/tau2)
    const float cP2 = (float)1.3591409142295225;    // e/tau2
    const float rR2 = (float)0.6065306597126334;    // exp(-1/tauRef2)
    const float cR2 = (float)(-54.365636569180902); // -scaleRef*theta2*e/tauRef2
    const float th2 = 40.0f;

    const int PGRID = NPIX / (PW_WARPS * 32);   // 2048
    dim3 cgrid(WWD / 32, HHT, NBATCH);          // (4,128,8)

    psp_kernel      <<<PGRID, 256, PW_SMEM>>>(x, bufA, r1, cP1);
    conv_kernel<5,2><<<cgrid, 416, SMEM5>>>(bufA, w1, bufB);
    spike_psp_kernel<<<PGRID, 256, PW_SMEM>>>(bufB, bufA, rR1, cR1, th1, r2, cP2);
    conv_kernel<3,4><<<cgrid, 416, SMEM3>>>(bufA, w2, bufB);
    spike_out_kernel<<<PGRID, 256, PW_SMEM>>>(bufB, outp, rR2, cR2, th2);
}

// round 3
// speedup vs baseline: 2.8993x; 1.2294x over previous
#include <cuda_runtime.h>

#define CHN   4
#define HHT   128
#define WWD   128
#define TT    50
#define TP    52          // padded t-stride: mult of 4 (LDS.128) & conflict-free (13 odd)
#define SOP   51          // staging row stride: gcd(51,32)=1 -> conflict-free scalar
#define NBATCH 8
#define NPIX  (NBATCH*CHN*HHT*WWD)   // 524288
#define NELEM (NPIX*TT)              // 26214400

__device__ float g_bufA[NELEM];
__device__ float g_bufB[NELEM];

// packed fp32x2 FMA (2 independent fp32 FMAs per instruction; bit-exact)
__device__ __forceinline__ void fma2(unsigned long long& d,
                                     unsigned long long a, unsigned long long b) {
    asm("fma.rn.f32x2 %0, %1, %2, %0;" : "+l"(d) : "l"(a), "l"(b));
}
__device__ __forceinline__ float2 upk(unsigned long long v) {
    float2 f;
    f.x = __uint_as_float((unsigned)(v & 0xffffffffull));
    f.y = __uint_as_float((unsigned)(v >> 32));
    return f;
}

// ---------------------------------------------------------------------------
// Standalone alpha-PSP (layer 1 input). Warp-local smem transpose.
// ---------------------------------------------------------------------------
#define PW_PAD 53
#define PW_WARPS 8
#define PW_SMEM (PW_WARPS * 32 * PW_PAD * 4)

__global__ void __launch_bounds__(256, 4) psp_kernel(const float* __restrict__ in,
                                                     float* __restrict__ out,
                                                     float r, float coef) {
    extern __shared__ float sm[];
    const int lane = threadIdx.x & 31;
    const int wrp  = threadIdx.x >> 5;
    float* ws = sm + wrp * 32 * PW_PAD;
    const long base = (long)(blockIdx.x * (PW_WARPS * 32) + wrp * 32) * TT;
    const float* g = in + base;
#pragma unroll
    for (int w = 0; w < 32; ++w) {
        ws[w * PW_PAD + lane] = g[w * TT + lane];
        if (lane < TT - 32) ws[w * PW_PAD + 32 + lane] = g[w * TT + 32 + lane];
    }
    __syncwarp();
    float* row = ws + lane * PW_PAD;
    float s1 = 0.f, s2 = 0.f;
#pragma unroll
    for (int t = 0; t < TT; ++t) {
        float x = row[t];
        row[t] = coef * s2;
        s1 = fmaf(r, s1, x);
        s2 = fmaf(r, s2, r * s1);
    }
    __syncwarp();
    float* o = out + base;
#pragma unroll
    for (int w = 0; w < 32; ++w) {
        o[w * TT + lane] = ws[w * PW_PAD + lane];
        if (lane < TT - 32) o[w * TT + 32 + lane] = ws[w * PW_PAD + 32 + lane];
    }
}

// ---------------------------------------------------------------------------
// Fused conv(KxK, 4->4, pad K/2) + spike-dynamics epilogue.
// EPI=0: epilogue = spike + next-layer psp (membrane from conv output).
// EPI=1: epilogue = spike only (binary output).
// Block = (32w, h, n), 416 thr = 13 warps. ci in passes of CIH channels.
// Compute: thread (wl, wrp) accumulates 4 co x 4 t via fma.rn.f32x2.
// SMEM: s_in [CIH][K][WH][TP]; s_w dup [ci][kh][kw][co dup x2]; s_out overlay
// [co][w][SOP=51] (conflict-free for the per-pixel recurrence).
// ---------------------------------------------------------------------------
template <int K, int CIH, int EPI>
__global__ void __launch_bounds__(416, 3)
conv_fused_kernel(const float* __restrict__ in, const float* __restrict__ wts,
                  float* __restrict__ out,
                  float rR, float cR, float theta, float rP, float cP) {
    constexpr int PAD = K / 2;
    constexpr int WH  = 32 + 2 * PAD;
    constexpr int NT  = 416;
    constexpr int SIN = CIH * K * WH * TP;
    constexpr int NW  = CHN * CHN * K * K;

    extern __shared__ float sm[];
    float* s_in = sm;
    float* s_w  = sm + SIN;

    const int tid  = threadIdx.x;
    const int lane = tid & 31;
    const int wrp  = tid >> 5;
    const int w0   = blockIdx.x * 32;
    const int h    = blockIdx.y;
    const int n    = blockIdx.z;

    // weights OIHW -> smem [(ci,kh,kw)][co*2 dup]
    if (tid < NW) {
        int co = tid / (CHN * K * K);
        int r  = tid % (CHN * K * K);
        float v = wts[tid];
        s_w[r * 8 + co * 2 + 0] = v;
        s_w[r * 8 + co * 2 + 1] = v;
    }

    const int t0 = wrp * 4;

    // acc2[co][half]: half0 = (t0,t0+1), half1 = (t0+2,t0+3)
    unsigned long long acc2[4][2];
#pragma unroll
    for (int c = 0; c < 4; ++c) { acc2[c][0] = 0ull; acc2[c][1] = 0ull; }

#pragma unroll
    for (int cib = 0; cib < CHN; cib += CIH) {
        for (int e = tid; e < SIN; e += NT) s_in[e] = 0.f;
        __syncthreads();
        for (int ci = 0; ci < CIH; ++ci) {
#pragma unroll
            for (int kh = 0; kh < K; ++kh) {
                int hh = h + kh - PAD;
                if (hh < 0 || hh >= HHT) continue;
                const float* src = in + (((long)(n * CHN + cib + ci) * HHT + hh) * WWD + (w0 - PAD)) * TT;
                float* dst = s_in + (ci * K + kh) * WH * TP;
                for (int row = wrp; row < WH; row += 13) {
                    int wg = w0 - PAD + row;
                    if (wg >= 0 && wg < WWD) {
                        dst[row * TP + lane] = src[row * TT + lane];
                        if (lane < TT - 32)
                            dst[row * TP + 32 + lane] = src[row * TT + 32 + lane];
                    }
                }
            }
        }
        __syncthreads();
#pragma unroll
        for (int ci = 0; ci < CIH; ++ci) {
#pragma unroll
            for (int kh = 0; kh < K; ++kh) {
                const float* rowp = s_in + ((ci * K + kh) * WH + lane) * TP + t0;
                const float* wp   = s_w + ((cib + ci) * K + kh) * K * 8;
#pragma unroll
                for (int kw = 0; kw < K; ++kw) {
                    const ulonglong2 iv = *reinterpret_cast<const ulonglong2*>(rowp + kw * TP);
                    const ulonglong2 wa = *reinterpret_cast<const ulonglong2*>(wp + kw * 8);     // (w0w0,w1w1)
                    const ulonglong2 wb = *reinterpret_cast<const ulonglong2*>(wp + kw * 8 + 4); // (w2w2,w3w3)
                    fma2(acc2[0][0], iv.x, wa.x);
                    fma2(acc2[0][1], iv.y, wa.x);
                    fma2(acc2[1][0], iv.x, wa.y);
                    fma2(acc2[1][1], iv.y, wa.y);
                    fma2(acc2[2][0], iv.x, wb.x);
                    fma2(acc2[2][1], iv.y, wb.x);
                    fma2(acc2[3][0], iv.x, wb.y);
                    fma2(acc2[3][1], iv.y, wb.y);
                }
            }
        }
        __syncthreads();
    }

    // stage conv results: s_out[co][w][t], row stride SOP=51 (conflict-free)
    float* s_out = sm;  // overlay: 4*32*51 = 6528 floats < SIN
#pragma unroll
    for (int co = 0; co < 4; ++co) {
        float* p = s_out + co * (32 * SOP) + lane * SOP + t0;
        float2 a = upk(acc2[co][0]);
        float2 b = upk(acc2[co][1]);
        p[0] = a.x;               // t0   <= 48 always valid
        p[1] = a.y;               // t0+1 <= 49 always valid
        if (t0 + 2 < TT) p[2] = b.x;
        if (t0 + 3 < TT) p[3] = b.y;
    }
    __syncthreads();

    // fused spike-dynamics epilogue: 128 pixels (4 co x 32 w), conflict-free rows
    if (tid < 128) {
        const int co = tid >> 5;
        const int w  = tid & 31;
        float* row = s_out + co * (32 * SOP) + w * SOP;
        float sd1 = 0.f, sd2 = 0.f, sp1 = 0.f, sp2 = 0.f;
#pragma unroll
        for (int t = 0; t < TT; ++t) {
            float m = fmaf(cR, sd2, row[t]);
            float s = (m >= theta) ? 1.f : 0.f;
            sd1 = fmaf(rR, sd1, s);
            sd2 = fmaf(rR, sd2, rR * sd1);
            if (EPI == 0) {
                row[t] = cP * sp2;
                sp1 = fmaf(rP, sp1, s);
                sp2 = fmaf(rP, sp2, rP * sp1);
            } else {
                row[t] = s;
            }
        }
    }
    __syncthreads();

    // coalesced global store
    for (int e = tid; e < 4 * 32 * TT; e += NT) {
        int co  = e / (32 * TT);
        int rem = e - co * (32 * TT);    // = w*TT + t
        int w   = rem / TT;
        int t   = rem - w * TT;
        out[(((long)(n * CHN + co) * HHT + h) * WWD + w0) * TT + rem] =
            s_out[co * (32 * SOP) + w * SOP + t];
    }
}

// ---------------------------------------------------------------------------

extern "C" void kernel_launch(void* const* d_in, const int* in_sizes, int n_in,
                              void* d_out, int out_size) {
    const float* x  = (const float*)d_in[0];
    const float* w1 = (const float*)d_in[1];
    const float* w2 = (const float*)d_in[2];
    float* outp = (float*)d_out;

    float *bufA, *bufB;
    cudaGetSymbolAddress((void**)&bufA, g_bufA);
    cudaGetSymbolAddress((void**)&bufB, g_bufB);

    // smem: conv5 CIH=1: 1*5*36*52*4 + 4*25*8*4 = 37440 + 3200 = 40640 B (x3/SM ok)
    //       conv3 CIH=2: 2*3*34*52*4 + 4*9*8*4  = 42432 + 1152 = 43584 B (x3/SM ok)
    const int SMEM5 = 1 * 5 * 36 * TP * 4 + CHN * 25 * 8 * 4;
    const int SMEM3 = 2 * 3 * 34 * TP * 4 + CHN * 9 * 8 * 4;
    cudaFuncSetAttribute((const void*)conv_fused_kernel<5, 1, 0>,
                         cudaFuncAttributeMaxDynamicSharedMemorySize, SMEM5);
    cudaFuncSetAttribute((const void*)conv_fused_kernel<3, 2, 1>,
                         cudaFuncAttributeMaxDynamicSharedMemorySize, SMEM3);
    cudaFuncSetAttribute((const void*)psp_kernel,
                         cudaFuncAttributeMaxDynamicSharedMemorySize, PW_SMEM);

    const float r1  = (float)0.36787944117144233;   // exp(-1/tau1)
    const float cP1 = (float)2.718281828459045;     // e/tau1
    const float rR1 = (float)0.36787944117144233;   // exp(-1/tauRef1)
    const float cR1 = (float)(-54.365636569180902); // -scaleRef*theta1*e/tauRef1
    const float th1 = 20.0f;
    const float r2  = (float)0.6065306597126334;    // exp(-1/tau2)
    const float cP2 = (float)1.3591409142295225;    // e/tau2
    const float rR2 = (float)0.6065306597126334;    // exp(-1/tauRef2)
    const float cR2 = (float)(-54.365636569180902); // -scaleRef*theta2*e/tauRef2
    const float th2 = 40.0f;

    const int PGRID = NPIX / (PW_WARPS * 32);   // 2048
    dim3 cgrid(WWD / 32, HHT, NBATCH);          // (4,128,8)

    // psp1 -> conv1 (+spike1 +psp2) -> conv2 (+spike2 -> out)
    psp_kernel<<<PGRID, 256, PW_SMEM>>>(x, bufA, r1, cP1);
    conv_fused_kernel<5, 1, 0><<<cgrid, 416, SMEM5>>>(bufA, w1, bufB,
                                                      rR1, cR1, th1, r2, cP2);
    conv_fused_kernel<3, 2, 1><<<cgrid, 416, SMEM3>>>(bufB, w2, outp,
                                                      rR2, cR2, th2, 0.f, 0.f);
}